// round 4
// baseline (speedup 1.0000x reference)
#include <cuda_runtime.h>

#define BATCH    256
#define NTHREADS 256

typedef unsigned long long ull;

// ---------------- device scratch (no allocations allowed) ----------------
// pair-duplicated weights: [o][c][g][20] floats = 9 x (w,w) pairs + 2 pad
__device__ __align__(16) float g_W1[8  * 3  * 7 * 20];   // 3360
__device__ __align__(16) float g_W2[16 * 8  * 7 * 20];   // 17920
__device__ __align__(16) float g_W3[32 * 16 * 7 * 20];   // 71680
__device__ float g_lwT[512 * 100];                       // 51200

// ---------------- packed f32x2 helpers ----------------
__device__ __forceinline__ ull pk(float lo, float hi) {
    ull r;
    asm("mov.b64 %0, {%1, %2};" : "=l"(r) : "f"(lo), "f"(hi));
    return r;
}
__device__ __forceinline__ void upk(ull v, float& lo, float& hi) {
    asm("mov.b64 {%0, %1}, %2;" : "=f"(lo), "=f"(hi) : "l"(v));
}
__device__ __forceinline__ void ffma2(ull& acc, ull a, ull b) {
    asm("fma.rn.f32x2 %0, %1, %2, %0;" : "+l"(acc) : "l"(a), "l"(b));
}

// ---------------- spline/silu feature expansion ----------------
__device__ __forceinline__ void compute_phi(float v, float* phi) {
    const float h = 2.0f / 3.0f;
    float b[9];
#pragma unroll
    for (int i = 0; i < 9; i++) {
        float t0 = (i - 3) * h - 1.0f;
        float t1 = (i - 2) * h - 1.0f;
        b[i] = (v >= t0 && v < t1) ? 1.0f : 0.0f;
    }
#pragma unroll
    for (int j = 1; j <= 3; j++) {
        float inv = 1.0f / (j * h);
#pragma unroll
        for (int i = 0; i + j < 9; i++) {
            float ti  = (i - 3) * h - 1.0f;
            float tj1 = (i + j - 2) * h - 1.0f;
            b[i] = (v - ti) * inv * b[i] + (tj1 - v) * inv * b[i + 1];
        }
    }
    phi[0] = v / (1.0f + __expf(-v));
#pragma unroll
    for (int g = 0; g < 6; g++) phi[g + 1] = b[g];
}

// ---------------- prep: fold scaler, duplicate into pairs, transpose linw ----------------
template <int O, int C>
__device__ __forceinline__ void fold_w(float* Wd, int i, const float* __restrict__ bw,
                                       const float* __restrict__ sw, const float* __restrict__ sc) {
    // i indexes pairs: [o][c][g][10 pairs]
    int p = i % 10;
    int g = (i / 10) % 7;
    int c = (i / 70) % C;
    int o = i / (70 * C);
    float val = 0.0f;
    if (p < 9) {
        int f = c * 9 + p;
        constexpr int F = C * 9;
        val = (g == 0) ? bw[o * F + f] : sw[(o * F + f) * 6 + (g - 1)] * sc[o * F + f];
    }
    Wd[i * 2]     = val;
    Wd[i * 2 + 1] = val;
}

#define NP1 (8 * 3 * 7 * 10)     // 1680
#define NP2 (16 * 8 * 7 * 10)    // 8960
#define NP3 (32 * 16 * 7 * 10)   // 35840
#define NPL (512 * 100)          // 51200
#define NPREP (NP1 + NP2 + NP3 + NPL)

__global__ void prep_all(
    const float* __restrict__ c1bw, const float* __restrict__ c1sw, const float* __restrict__ c1sc,
    const float* __restrict__ c2bw, const float* __restrict__ c2sw, const float* __restrict__ c2sc,
    const float* __restrict__ c3bw, const float* __restrict__ c3sw, const float* __restrict__ c3sc,
    const float* __restrict__ linw)
{
    int i = blockIdx.x * blockDim.x + threadIdx.x;
    if (i < NP1) {
        fold_w<8, 3>(g_W1, i, c1bw, c1sw, c1sc);
    } else if (i < NP1 + NP2) {
        fold_w<16, 8>(g_W2, i - NP1, c2bw, c2sw, c2sc);
    } else if (i < NP1 + NP2 + NP3) {
        fold_w<32, 16>(g_W3, i - NP1 - NP2, c3bw, c3sw, c3sc);
    } else if (i < NPREP) {
        int k = i - NP1 - NP2 - NP3;
        int j = k / 512, f = k % 512;
        g_lwT[f * 100 + j] = linw[j * 512 + f];
    }
}

// ---------------- one fused KAN conv3x3 + maxpool2 phase ----------------
// E layout: [c][y][g][x], Xd = W+2 (even -> float2-aligned e loads).
// Packed f32x2 FMA: accumulator pair = conv outputs (x=2px, 2px+1).
template <int C, int H, int W, int O, int OT, bool ING>
__device__ __forceinline__ void kan_layer(
    const float* __restrict__ gin, const float* sin_,
    float* outb, float* E, const float* __restrict__ Wg, int tid)
{
    constexpr int PH = H / 2, PW = W / 2, Yd = H + 2, Xd = W + 2;

    // ---- phi expansion over padded input ----
    for (int i = tid; i < C * Yd * Xd; i += NTHREADS) {
        int x = i % Xd;
        int y = (i / Xd) % Yd;
        int c = i / (Xd * Yd);
        float v = 0.0f;
        if (y >= 1 && y <= H && x >= 1 && x <= W) {
            int idx = (c * H + y - 1) * W + x - 1;
            v = ING ? __ldg(&gin[idx]) : sin_[idx];
        }
        float phi[7];
        compute_phi(v, phi);
#pragma unroll
        for (int g = 0; g < 7; g++) E[((c * Yd + y) * 7 + g) * Xd + x] = phi[g];
    }
    __syncthreads();

    // ---- conv + fused 2x2 maxpool, packed over x ----
    const int px = tid % PW;
    const int py = (tid / PW) % PH;
    const int og = tid / (PW * PH);

    ull accT[OT], accB[OT];
#pragma unroll
    for (int o = 0; o < OT; o++) { accT[o] = 0ULL; accB[o] = 0ULL; }

    for (int c = 0; c < C; c++) {
#pragma unroll
        for (int g = 0; g < 7; g++) {
            // e pairs per row: ea=(e0,e1), em=(e1,e2), eb=(e2,e3)
            ull ea[4], em[4], eb[4];
            const int base = ((c * Yd + 2 * py) * 7 + g) * Xd + 2 * px;
#pragma unroll
            for (int dy = 0; dy < 4; dy++) {
                const float2* r = reinterpret_cast<const float2*>(&E[base + dy * 7 * Xd]);
                float2 a = r[0], b2 = r[1];
                ea[dy] = pk(a.x, a.y);
                em[dy] = pk(a.y, b2.x);
                eb[dy] = pk(b2.x, b2.y);
            }
#pragma unroll
            for (int o = 0; o < OT; o++) {
                const ulonglong2* wv = reinterpret_cast<const ulonglong2*>(
                    &Wg[(((og * OT + o) * C + c) * 7 + g) * 20]);
                ulonglong2 p0 = __ldg(wv + 0);
                ulonglong2 p1 = __ldg(wv + 1);
                ulonglong2 p2 = __ldg(wv + 2);
                ulonglong2 p3 = __ldg(wv + 3);
                ulonglong2 p4 = __ldg(wv + 4);
                ull w[9] = {p0.x, p0.y, p1.x, p1.y, p2.x, p2.y, p3.x, p3.y, p4.x};
                ull aT = accT[o], aB = accB[o];
#pragma unroll
                for (int kh = 0; kh < 3; kh++) {
                    ffma2(aT, ea[kh],     w[3 * kh + 0]);
                    ffma2(aT, em[kh],     w[3 * kh + 1]);
                    ffma2(aT, eb[kh],     w[3 * kh + 2]);
                    ffma2(aB, ea[kh + 1], w[3 * kh + 0]);
                    ffma2(aB, em[kh + 1], w[3 * kh + 1]);
                    ffma2(aB, eb[kh + 1], w[3 * kh + 2]);
                }
                accT[o] = aT; accB[o] = aB;
            }
        }
    }

#pragma unroll
    for (int o = 0; o < OT; o++) {
        float t0, t1, b0, b1;
        upk(accT[o], t0, t1);
        upk(accB[o], b0, b1);
        float m = fmaxf(fmaxf(t0, t1), fmaxf(b0, b1));
        outb[((og * OT + o) * PH + py) * PW + px] = m;
    }
    __syncthreads();
}

// ---------------- fused whole-network kernel: block = image ----------------
// smem arena (floats):
//   out1 @ 0 (2048) | out2 @ 2048 (1024) | out3 @ 3072 (512) | E @ 3584 (max 24276)
#define OUT1_OFF 0
#define OUT2_OFF 2048
#define OUT3_OFF 3072
#define E_OFF    3584
#define SMEM_FLOATS (E_OFF + 3 * 34 * 7 * 34)

__global__ void __launch_bounds__(NTHREADS, 2) fused_kan(
    const float* __restrict__ x,
    const float* __restrict__ linb,
    float* __restrict__ out)
{
    extern __shared__ float sm[];
    const int b   = blockIdx.x;
    const int tid = threadIdx.x;

    kan_layer<3, 32, 32, 8, 8, true>(x + (size_t)b * 3072, nullptr,
                                     sm + OUT1_OFF, sm + E_OFF, g_W1, tid);
    kan_layer<8, 16, 16, 16, 4, false>(nullptr, sm + OUT1_OFF,
                                       sm + OUT2_OFF, sm + E_OFF, g_W2, tid);
    kan_layer<16, 8, 8, 32, 2, false>(nullptr, sm + OUT2_OFF,
                                      sm + OUT3_OFF, sm + E_OFF, g_W3, tid);

    // ---- final linear 512 -> 100 (h = out3 in smem) ----
    if (tid < 100) {
        float a = __ldg(&linb[tid]);
        const float* h = sm + OUT3_OFF;
#pragma unroll 8
        for (int f = 0; f < 512; f++) {
            a += h[f] * __ldg(&g_lwT[f * 100 + tid]);
        }
        out[(size_t)b * 100 + tid] = a;
    }
}

// ---------------- launch ----------------
extern "C" void kernel_launch(void* const* d_in, const int* in_sizes, int n_in,
                              void* d_out, int out_size) {
    const float* x     = (const float*)d_in[0];
    const float* c1bw  = (const float*)d_in[1];
    const float* c1sw  = (const float*)d_in[2];
    const float* c1sc  = (const float*)d_in[3];
    const float* c2bw  = (const float*)d_in[4];
    const float* c2sw  = (const float*)d_in[5];
    const float* c2sc  = (const float*)d_in[6];
    const float* c3bw  = (const float*)d_in[7];
    const float* c3sw  = (const float*)d_in[8];
    const float* c3sc  = (const float*)d_in[9];
    const float* linw  = (const float*)d_in[10];
    const float* linb  = (const float*)d_in[11];
    float* out = (float*)d_out;

    static bool attr_set = false;
    if (!attr_set) {
        cudaFuncSetAttribute(fused_kan, cudaFuncAttributeMaxDynamicSharedMemorySize,
                             SMEM_FLOATS * 4);
        attr_set = true;
    }

    prep_all<<<(NPREP + 255) / 256, 256>>>(c1bw, c1sw, c1sc, c2bw, c2sw, c2sc,
                                           c3bw, c3sw, c3sc, linw);
    fused_kan<<<BATCH, NTHREADS, SMEM_FLOATS * 4>>>(x, linb, out);
}

// round 5
// speedup vs baseline: 1.1540x; 1.1540x over previous
#include <cuda_runtime.h>

#define BATCH 256

// ---------------- device scratch (no allocations allowed) ----------------
__device__ float g_W1[8  * 3  * 7 * 12];   // 2016
__device__ float g_W2[16 * 8  * 7 * 12];   // 10752
__device__ float g_W3[32 * 16 * 7 * 12];   // 43008
__device__ float g_lwT[512 * 100];         // 51200
__device__ float g_out1[BATCH * 8  * 16 * 16];
__device__ float g_out2[BATCH * 16 * 8 * 8];
__device__ float g_out3[BATCH * 32 * 4 * 4];

// ---------------- spline/silu feature expansion ----------------
__device__ __forceinline__ void compute_phi(float v, float* phi) {
    const float h = 2.0f / 3.0f;
    float b[9];
#pragma unroll
    for (int i = 0; i < 9; i++) {
        float t0 = (i - 3) * h - 1.0f;
        float t1 = (i - 2) * h - 1.0f;
        b[i] = (v >= t0 && v < t1) ? 1.0f : 0.0f;
    }
#pragma unroll
    for (int j = 1; j <= 3; j++) {
        float inv = 1.0f / (j * h);
#pragma unroll
        for (int i = 0; i + j < 9; i++) {
            float ti  = (i - 3) * h - 1.0f;
            float tj1 = (i + j - 2) * h - 1.0f;
            b[i] = (v - ti) * inv * b[i] + (tj1 - v) * inv * b[i + 1];
        }
    }
    phi[0] = v / (1.0f + __expf(-v));
#pragma unroll
    for (int g = 0; g < 6; g++) phi[g + 1] = b[g];
}

// ---------------- prep: fold scaler into [o][c][g][12], transpose linw ----------------
template <int O, int C>
__device__ __forceinline__ void fold_w(float* Wd, int i, const float* __restrict__ bw,
                                       const float* __restrict__ sw, const float* __restrict__ sc) {
    int kp = i % 12;
    int g  = (i / 12) % 7;
    int c  = (i / 84) % C;
    int o  = i / (84 * C);
    float val = 0.0f;
    if (kp < 9) {
        int f = c * 9 + kp;
        constexpr int F = C * 9;
        val = (g == 0) ? bw[o * F + f] : sw[(o * F + f) * 6 + (g - 1)] * sc[o * F + f];
    }
    Wd[i] = val;
}

#define NPREP (2016 + 10752 + 43008 + 51200)

__global__ void prep_all(
    const float* __restrict__ c1bw, const float* __restrict__ c1sw, const float* __restrict__ c1sc,
    const float* __restrict__ c2bw, const float* __restrict__ c2sw, const float* __restrict__ c2sc,
    const float* __restrict__ c3bw, const float* __restrict__ c3sw, const float* __restrict__ c3sc,
    const float* __restrict__ linw)
{
    int i = blockIdx.x * blockDim.x + threadIdx.x;
    if (i < 2016) {
        fold_w<8, 3>(g_W1, i, c1bw, c1sw, c1sc);
    } else if (i < 2016 + 10752) {
        fold_w<16, 8>(g_W2, i - 2016, c2bw, c2sw, c2sc);
    } else if (i < 2016 + 10752 + 43008) {
        fold_w<32, 16>(g_W3, i - 12768, c3bw, c3sw, c3sc);
    } else if (i < NPREP) {
        int k = i - 55776;
        int j = k / 512, f = k % 512;
        g_lwT[f * 100 + j] = linw[j * 512 + f];
    }
}

// ---------------- per-layer strip kernel: conv3x3 over expanded phi + maxpool2 ----------------
// Block = SR pooled rows of one image. E layout [c][ly][g][x], Xd = W+2, Yd = 2*SR+2.
// Thread = (pooled x, strip-local pooled row, group of OT output channels). 128 threads.
template <int C, int H, int W, int O, int OT, int SR>
__global__ void __launch_bounds__(128) kan_layer(
    const float* __restrict__ in, float* __restrict__ out, const float* __restrict__ Wg)
{
    constexpr int PW = W / 2, PH = H / 2;
    constexpr int OG = O / OT;
    constexpr int STRIPS = PH / SR;
    constexpr int Yd = 2 * SR + 2, Xd = W + 2;
    constexpr int THREADS = PW * SR * OG;   // = 128 for all layers

    extern __shared__ float E[];

    const int blk = blockIdx.x;
    const int b   = blk / STRIPS;
    const int s   = blk % STRIPS;
    const int tid = threadIdx.x;

    // ---- phi expansion over the strip's padded input rows ----
    const float* inb = in + (size_t)b * C * H * W;
    const int gy0 = 2 * s * SR - 1;
    for (int i = tid; i < C * Yd * Xd; i += THREADS) {
        int x  = i % Xd;
        int ly = (i / Xd) % Yd;
        int c  = i / (Xd * Yd);
        int gy = gy0 + ly;
        float v = 0.0f;
        if (gy >= 0 && gy < H && x >= 1 && x <= W) v = __ldg(&inb[(c * H + gy) * W + x - 1]);
        float phi[7];
        compute_phi(v, phi);
#pragma unroll
        for (int g = 0; g < 7; g++) E[((c * Yd + ly) * 7 + g) * Xd + x] = phi[g];
    }
    __syncthreads();

    // ---- conv + fused 2x2 maxpool ----
    const int px = tid % PW;
    const int pr = (tid / PW) % SR;
    const int og = tid / (PW * SR);

    float acc[OT][4];
#pragma unroll
    for (int o = 0; o < OT; o++) acc[o][0] = acc[o][1] = acc[o][2] = acc[o][3] = 0.0f;

    for (int c = 0; c < C; c++) {
#pragma unroll
        for (int g = 0; g < 7; g++) {
            float e[4][4];
            const int base = ((c * Yd + 2 * pr) * 7 + g) * Xd + 2 * px;
#pragma unroll
            for (int dy = 0; dy < 4; dy++) {
                const float2* r = reinterpret_cast<const float2*>(&E[base + dy * 7 * Xd]);
                float2 a = r[0], b2 = r[1];
                e[dy][0] = a.x; e[dy][1] = a.y; e[dy][2] = b2.x; e[dy][3] = b2.y;
            }
#pragma unroll
            for (int o = 0; o < OT; o++) {
                const float4* wv = reinterpret_cast<const float4*>(
                    &Wg[(((og * OT + o) * C + c) * 7 + g) * 12]);
                float4 w0 = __ldg(&wv[0]);
                float4 w1 = __ldg(&wv[1]);
                float4 w2 = __ldg(&wv[2]);
                float wk[9] = {w0.x, w0.y, w0.z, w0.w, w1.x, w1.y, w1.z, w1.w, w2.x};
#pragma unroll
                for (int kh = 0; kh < 3; kh++)
#pragma unroll
                    for (int kw = 0; kw < 3; kw++) {
                        float wgt = wk[kh * 3 + kw];
                        acc[o][0] += e[kh][kw] * wgt;
                        acc[o][1] += e[kh][kw + 1] * wgt;
                        acc[o][2] += e[kh + 1][kw] * wgt;
                        acc[o][3] += e[kh + 1][kw + 1] * wgt;
                    }
            }
        }
    }

    float* outb = out + (size_t)b * O * PH * PW;
    const int prow = s * SR + pr;
#pragma unroll
    for (int o = 0; o < OT; o++) {
        float m = fmaxf(fmaxf(acc[o][0], acc[o][1]), fmaxf(acc[o][2], acc[o][3]));
        outb[((og * OT + o) * PH + prow) * PW + px] = m;
    }
}

// helper to get raw pointers to __device__ arrays inside kernels
__global__ void __launch_bounds__(128) linear_k(const float* __restrict__ bias,
                                                float* __restrict__ out) {
    __shared__ float hs[512];
    int b = blockIdx.x;
    for (int i = threadIdx.x; i < 512; i += 128) hs[i] = g_out3[b * 512 + i];
    __syncthreads();
    int j = threadIdx.x;
    if (j < 100) {
        float a = __ldg(&bias[j]);
#pragma unroll 8
        for (int f = 0; f < 512; f++) a += hs[f] * __ldg(&g_lwT[f * 100 + j]);
        out[(size_t)b * 100 + j] = a;
    }
}

// device-pointer trampolines (cannot take address of __device__ arrays on host portably
// without cudaGetSymbolAddress, which is fine outside capture but we just launch with
// kernels referencing the globals directly via wrapper kernels below)
__global__ void __launch_bounds__(128) kan_l1(const float* __restrict__ x) {
    // never called; placeholder
}

extern "C" void kernel_launch(void* const* d_in, const int* in_sizes, int n_in,
                              void* d_out, int out_size) {
    const float* x     = (const float*)d_in[0];
    const float* c1bw  = (const float*)d_in[1];
    const float* c1sw  = (const float*)d_in[2];
    const float* c1sc  = (const float*)d_in[3];
    const float* c2bw  = (const float*)d_in[4];
    const float* c2sw  = (const float*)d_in[5];
    const float* c2sc  = (const float*)d_in[6];
    const float* c3bw  = (const float*)d_in[7];
    const float* c3sw  = (const float*)d_in[8];
    const float* c3sc  = (const float*)d_in[9];
    const float* linw  = (const float*)d_in[10];
    const float* linb  = (const float*)d_in[11];
    float* out = (float*)d_out;

    static float *p_W1, *p_W2, *p_W3, *p_o1, *p_o2, *p_o3;
    static bool init = false;
    if (!init) {
        cudaGetSymbolAddress((void**)&p_W1, g_W1);
        cudaGetSymbolAddress((void**)&p_W2, g_W2);
        cudaGetSymbolAddress((void**)&p_W3, g_W3);
        cudaGetSymbolAddress((void**)&p_o1, g_out1);
        cudaGetSymbolAddress((void**)&p_o2, g_out2);
        cudaGetSymbolAddress((void**)&p_o3, g_out3);
        init = true;
    }

    prep_all<<<(NPREP + 255) / 256, 256>>>(c1bw, c1sw, c1sc, c2bw, c2sw, c2sc,
                                           c3bw, c3sw, c3sc, linw);

    // L1: C=3 H=W=32 O=8  OT=4 SR=4  -> 4 strips/img, grid 1024, smem 3*10*7*34
    kan_layer<3, 32, 32, 8, 4, 4><<<BATCH * 4, 128, 3 * 10 * 7 * 34 * 4>>>(x, p_o1, p_W1);
    // L2: C=8 H=W=16 O=16 OT=4 SR=4  -> 2 strips/img, grid 512,  smem 8*10*7*18
    kan_layer<8, 16, 16, 16, 4, 4><<<BATCH * 2, 128, 8 * 10 * 7 * 18 * 4>>>(p_o1, p_o2, p_W2);
    // L3: C=16 H=W=8 O=32 OT=2 SR=2  -> 2 strips/img, grid 512,  smem 16*6*7*10
    kan_layer<16, 8, 8, 32, 2, 2><<<BATCH * 2, 128, 16 * 6 * 7 * 10 * 4>>>(p_o2, p_o3, p_W3);

    linear_k<<<BATCH, 128>>>(linb, out);
}

// round 6
// speedup vs baseline: 1.2161x; 1.0538x over previous
#include <cuda_runtime.h>

#define BATCH 256

// ---------------- device scratch (no allocations allowed) ----------------
__device__ float g_W1[8  * 3  * 7 * 12];   // 2016
__device__ float g_W2[16 * 8  * 7 * 12];   // 10752
__device__ float g_W3[32 * 16 * 7 * 12];   // 43008
__device__ float g_lwT[512 * 100];         // 51200
__device__ float g_out1[BATCH * 8  * 16 * 16];
__device__ float g_out2[BATCH * 16 * 8 * 8];
__device__ float g_out3[BATCH * 32 * 4 * 4];

// ---------------- spline/silu feature expansion ----------------
__device__ __forceinline__ void compute_phi(float v, float* phi) {
    const float h = 2.0f / 3.0f;
    float b[9];
#pragma unroll
    for (int i = 0; i < 9; i++) {
        float t0 = (i - 3) * h - 1.0f;
        float t1 = (i - 2) * h - 1.0f;
        b[i] = (v >= t0 && v < t1) ? 1.0f : 0.0f;
    }
#pragma unroll
    for (int j = 1; j <= 3; j++) {
        float inv = 1.0f / (j * h);
#pragma unroll
        for (int i = 0; i + j < 9; i++) {
            float ti  = (i - 3) * h - 1.0f;
            float tj1 = (i + j - 2) * h - 1.0f;
            b[i] = (v - ti) * inv * b[i] + (tj1 - v) * inv * b[i + 1];
        }
    }
    phi[0] = v / (1.0f + __expf(-v));
#pragma unroll
    for (int g = 0; g < 6; g++) phi[g + 1] = b[g];
}

// ---------------- prep: fold scaler into [o][c][g][12], transpose linw ----------------
template <int O, int C>
__device__ __forceinline__ void fold_w(float* Wd, int i, const float* __restrict__ bw,
                                       const float* __restrict__ sw, const float* __restrict__ sc) {
    int kp = i % 12;
    int g  = (i / 12) % 7;
    int c  = (i / 84) % C;
    int o  = i / (84 * C);
    float val = 0.0f;
    if (kp < 9) {
        int f = c * 9 + kp;
        constexpr int F = C * 9;
        val = (g == 0) ? bw[o * F + f] : sw[(o * F + f) * 6 + (g - 1)] * sc[o * F + f];
    }
    Wd[i] = val;
}

#define NPREP (2016 + 10752 + 43008 + 51200)

__global__ void prep_all(
    const float* __restrict__ c1bw, const float* __restrict__ c1sw, const float* __restrict__ c1sc,
    const float* __restrict__ c2bw, const float* __restrict__ c2sw, const float* __restrict__ c2sc,
    const float* __restrict__ c3bw, const float* __restrict__ c3sw, const float* __restrict__ c3sc,
    const float* __restrict__ linw)
{
    int i = blockIdx.x * blockDim.x + threadIdx.x;
    if (i < 2016) {
        fold_w<8, 3>(g_W1, i, c1bw, c1sw, c1sc);
    } else if (i < 2016 + 10752) {
        fold_w<16, 8>(g_W2, i - 2016, c2bw, c2sw, c2sc);
    } else if (i < 2016 + 10752 + 43008) {
        fold_w<32, 16>(g_W3, i - 12768, c3bw, c3sw, c3sc);
    } else if (i < NPREP) {
        int k = i - 55776;
        int j = k / 512, f = k % 512;
        g_lwT[f * 100 + j] = linw[j * 512 + f];
    }
}

// ---------------- per-layer strip kernel: conv3x3 over expanded phi + maxpool2 ----------------
// Block = SR pooled rows of one image, 64 threads. E layout [c][ly][g][x].
// Thread = (pooled x, strip-local pooled row, group of OT output channels).
template <int C, int H, int W, int O, int OT, int SR>
__global__ void __launch_bounds__(64, 8) kan_layer(
    const float* __restrict__ in, float* __restrict__ out, const float* __restrict__ Wg)
{
    constexpr int PW = W / 2, PH = H / 2;
    constexpr int OG = O / OT;
    constexpr int STRIPS = PH / SR;
    constexpr int Yd = 2 * SR + 2, Xd = W + 2;
    constexpr int THREADS = PW * SR * OG;
    static_assert(THREADS == 64, "block must be 64 threads");

    extern __shared__ float E[];

    const int blk = blockIdx.x;
    const int b   = blk / STRIPS;
    const int s   = blk % STRIPS;
    const int tid = threadIdx.x;

    // ---- phi expansion over the strip's padded input rows ----
    const float* inb = in + (size_t)b * C * H * W;
    const int gy0 = 2 * s * SR - 1;
    for (int i = tid; i < C * Yd * Xd; i += THREADS) {
        int x  = i % Xd;
        int ly = (i / Xd) % Yd;
        int c  = i / (Xd * Yd);
        int gy = gy0 + ly;
        float v = 0.0f;
        if (gy >= 0 && gy < H && x >= 1 && x <= W) v = __ldg(&inb[(c * H + gy) * W + x - 1]);
        float phi[7];
        compute_phi(v, phi);
#pragma unroll
        for (int g = 0; g < 7; g++) E[((c * Yd + ly) * 7 + g) * Xd + x] = phi[g];
    }
    __syncthreads();

    // ---- conv + fused 2x2 maxpool ----
    const int px = tid % PW;
    const int pr = (tid / PW) % SR;
    const int og = tid / (PW * SR);

    float acc[OT][4];
#pragma unroll
    for (int o = 0; o < OT; o++) acc[o][0] = acc[o][1] = acc[o][2] = acc[o][3] = 0.0f;

    for (int c = 0; c < C; c++) {
#pragma unroll
        for (int g = 0; g < 7; g++) {
            float e[4][4];
            const int base = ((c * Yd + 2 * pr) * 7 + g) * Xd + 2 * px;
#pragma unroll
            for (int dy = 0; dy < 4; dy++) {
                const float2* r = reinterpret_cast<const float2*>(&E[base + dy * 7 * Xd]);
                float2 a = r[0], b2 = r[1];
                e[dy][0] = a.x; e[dy][1] = a.y; e[dy][2] = b2.x; e[dy][3] = b2.y;
            }
#pragma unroll
            for (int o = 0; o < OT; o++) {
                const float4* wv = reinterpret_cast<const float4*>(
                    &Wg[(((og * OT + o) * C + c) * 7 + g) * 12]);
                float4 w0 = __ldg(&wv[0]);
                float4 w1 = __ldg(&wv[1]);
                float4 w2 = __ldg(&wv[2]);
                float wk[9] = {w0.x, w0.y, w0.z, w0.w, w1.x, w1.y, w1.z, w1.w, w2.x};
#pragma unroll
                for (int kh = 0; kh < 3; kh++)
#pragma unroll
                    for (int kw = 0; kw < 3; kw++) {
                        float wgt = wk[kh * 3 + kw];
                        acc[o][0] += e[kh][kw] * wgt;
                        acc[o][1] += e[kh][kw + 1] * wgt;
                        acc[o][2] += e[kh + 1][kw] * wgt;
                        acc[o][3] += e[kh + 1][kw + 1] * wgt;
                    }
            }
        }
    }

    float* outb = out + (size_t)b * O * PH * PW;
    const int prow = s * SR + pr;
#pragma unroll
    for (int o = 0; o < OT; o++) {
        float m = fmaxf(fmaxf(acc[o][0], acc[o][1]), fmaxf(acc[o][2], acc[o][3]));
        outb[((og * OT + o) * PH + prow) * PW + px] = m;
    }
}

// ---------------- final linear 512 -> 100 ----------------
__global__ void __launch_bounds__(128) linear_k(const float* __restrict__ bias,
                                                float* __restrict__ out) {
    __shared__ float hs[512];
    int b = blockIdx.x;
    for (int i = threadIdx.x; i < 512; i += 128) hs[i] = g_out3[b * 512 + i];
    __syncthreads();
    int j = threadIdx.x;
    if (j < 100) {
        float a = __ldg(&bias[j]);
#pragma unroll 8
        for (int f = 0; f < 512; f++) a += hs[f] * __ldg(&g_lwT[f * 100 + j]);
        out[(size_t)b * 100 + j] = a;
    }
}

extern "C" void kernel_launch(void* const* d_in, const int* in_sizes, int n_in,
                              void* d_out, int out_size) {
    const float* x     = (const float*)d_in[0];
    const float* c1bw  = (const float*)d_in[1];
    const float* c1sw  = (const float*)d_in[2];
    const float* c1sc  = (const float*)d_in[3];
    const float* c2bw  = (const float*)d_in[4];
    const float* c2sw  = (const float*)d_in[5];
    const float* c2sc  = (const float*)d_in[6];
    const float* c3bw  = (const float*)d_in[7];
    const float* c3sw  = (const float*)d_in[8];
    const float* c3sc  = (const float*)d_in[9];
    const float* linw  = (const float*)d_in[10];
    const float* linb  = (const float*)d_in[11];
    float* out = (float*)d_out;

    static float *p_W1, *p_W2, *p_W3, *p_o1, *p_o2, *p_o3;
    static bool init = false;
    if (!init) {
        cudaGetSymbolAddress((void**)&p_W1, g_W1);
        cudaGetSymbolAddress((void**)&p_W2, g_W2);
        cudaGetSymbolAddress((void**)&p_W3, g_W3);
        cudaGetSymbolAddress((void**)&p_o1, g_out1);
        cudaGetSymbolAddress((void**)&p_o2, g_out2);
        cudaGetSymbolAddress((void**)&p_o3, g_out3);
        init = true;
    }

    prep_all<<<(NPREP + 255) / 256, 256>>>(c1bw, c1sw, c1sc, c2bw, c2sw, c2sc,
                                           c3bw, c3sw, c3sc, linw);

    // L1: C=3 H=W=32 O=8  OT=8 SR=4 -> 64 thr, 4 strips, grid 1024, smem 28560 B
    kan_layer<3, 32, 32, 8, 8, 4><<<BATCH * 4, 64, 3 * 10 * 7 * 34 * 4>>>(x, p_o1, p_W1);
    // L2: C=8 H=W=16 O=16 OT=8 SR=4 -> 64 thr, 2 strips, grid 512, smem 40320 B
    kan_layer<8, 16, 16, 16, 8, 4><<<BATCH * 2, 64, 8 * 10 * 7 * 18 * 4>>>(p_o1, p_o2, p_W2);
    // L3: C=16 H=W=8 O=32 OT=4 SR=2 -> 64 thr, 2 strips, grid 512, smem 26880 B
    kan_layer<16, 8, 8, 32, 4, 2><<<BATCH * 2, 64, 16 * 6 * 7 * 10 * 4>>>(p_o2, p_o3, p_W3);

    linear_k<<<BATCH, 128>>>(linb, out);
}

// round 7
// speedup vs baseline: 1.3179x; 1.0837x over previous
#include <cuda_runtime.h>

#define BATCH 256

// ---------------- device scratch (no allocations allowed) ----------------
__device__ float g_W1[8  * 3  * 7 * 12];   // 2016
__device__ float g_W2[16 * 8  * 7 * 12];   // 10752
__device__ float g_W3[32 * 16 * 7 * 12];   // 43008
__device__ float g_out1[BATCH * 8  * 16 * 16];
__device__ float g_out2[BATCH * 16 * 8 * 8];
__device__ float g_out3[BATCH * 32 * 4 * 4];

// ---------------- spline/silu feature expansion ----------------
__device__ __forceinline__ void compute_phi(float v, float* phi) {
    const float h = 2.0f / 3.0f;
    float b[9];
#pragma unroll
    for (int i = 0; i < 9; i++) {
        float t0 = (i - 3) * h - 1.0f;
        float t1 = (i - 2) * h - 1.0f;
        b[i] = (v >= t0 && v < t1) ? 1.0f : 0.0f;
    }
#pragma unroll
    for (int j = 1; j <= 3; j++) {
        float inv = 1.0f / (j * h);
#pragma unroll
        for (int i = 0; i + j < 9; i++) {
            float ti  = (i - 3) * h - 1.0f;
            float tj1 = (i + j - 2) * h - 1.0f;
            b[i] = (v - ti) * inv * b[i] + (tj1 - v) * inv * b[i + 1];
        }
    }
    phi[0] = v / (1.0f + __expf(-v));
#pragma unroll
    for (int g = 0; g < 6; g++) phi[g + 1] = b[g];
}

// ---------------- prep: fold scaler into [o][c][g][12] ----------------
template <int O, int C>
__device__ __forceinline__ void fold_w(float* Wd, int i, const float* __restrict__ bw,
                                       const float* __restrict__ sw, const float* __restrict__ sc) {
    int kp = i % 12;
    int g  = (i / 12) % 7;
    int c  = (i / 84) % C;
    int o  = i / (84 * C);
    float val = 0.0f;
    if (kp < 9) {
        int f = c * 9 + kp;
        constexpr int F = C * 9;
        val = (g == 0) ? bw[o * F + f] : sw[(o * F + f) * 6 + (g - 1)] * sc[o * F + f];
    }
    Wd[i] = val;
}

#define NPREP (2016 + 10752 + 43008)

__global__ void prep_all(
    const float* __restrict__ c1bw, const float* __restrict__ c1sw, const float* __restrict__ c1sc,
    const float* __restrict__ c2bw, const float* __restrict__ c2sw, const float* __restrict__ c2sc,
    const float* __restrict__ c3bw, const float* __restrict__ c3sw, const float* __restrict__ c3sc)
{
    int i = blockIdx.x * blockDim.x + threadIdx.x;
    if (i < 2016) {
        fold_w<8, 3>(g_W1, i, c1bw, c1sw, c1sc);
    } else if (i < 2016 + 10752) {
        fold_w<16, 8>(g_W2, i - 2016, c2bw, c2sw, c2sc);
    } else if (i < NPREP) {
        fold_w<32, 16>(g_W3, i - 12768, c3bw, c3sw, c3sc);
    }
}

// ---------------- generic conv inner loop over CT channels ----------------
template <int CT, int OT, int Yd, int Xd>
__device__ __forceinline__ void conv_body(
    const float* E, const float* __restrict__ Wg, float acc[OT][4],
    int c0, int pr, int px, int og_base /* = (og*OT)*C + c0 channel-major offset helper */,
    int C_total)
{
#pragma unroll 1
    for (int cc = 0; cc < CT; cc++) {
        int c = c0 + cc;
#pragma unroll
        for (int g = 0; g < 7; g++) {
            float e[4][4];
            const int base = ((c * Yd + 2 * pr) * 7 + g) * Xd + 2 * px;
#pragma unroll
            for (int dy = 0; dy < 4; dy++) {
                const float2* r = reinterpret_cast<const float2*>(&E[base + dy * 7 * Xd]);
                float2 a = r[0], b2 = r[1];
                e[dy][0] = a.x; e[dy][1] = a.y; e[dy][2] = b2.x; e[dy][3] = b2.y;
            }
#pragma unroll
            for (int o = 0; o < OT; o++) {
                const float4* wv = reinterpret_cast<const float4*>(
                    &Wg[(((og_base + o * C_total) + c) * 7 + g) * 12]);
                float4 w0 = __ldg(&wv[0]);
                float4 w1 = __ldg(&wv[1]);
                float4 w2 = __ldg(&wv[2]);
                float wk[9] = {w0.x, w0.y, w0.z, w0.w, w1.x, w1.y, w1.z, w1.w, w2.x};
#pragma unroll
                for (int kh = 0; kh < 3; kh++)
#pragma unroll
                    for (int kw = 0; kw < 3; kw++) {
                        float wgt = wk[kh * 3 + kw];
                        acc[o][0] += e[kh][kw] * wgt;
                        acc[o][1] += e[kh][kw + 1] * wgt;
                        acc[o][2] += e[kh + 1][kw] * wgt;
                        acc[o][3] += e[kh + 1][kw + 1] * wgt;
                    }
            }
        }
    }
}

// ---------------- phi expansion of a strip into smem ----------------
template <int C, int H, int W, int SR, int THREADS>
__device__ __forceinline__ void expand_strip(
    const float* __restrict__ inb, float* E, int s, int tid)
{
    constexpr int Yd = 2 * SR + 2, Xd = W + 2;
    const int gy0 = 2 * s * SR - 1;
    for (int i = tid; i < C * Yd * Xd; i += THREADS) {
        int x  = i % Xd;
        int ly = (i / Xd) % Yd;
        int c  = i / (Xd * Yd);
        int gy = gy0 + ly;
        float v = 0.0f;
        if (gy >= 0 && gy < H && x >= 1 && x <= W) v = __ldg(&inb[(c * H + gy) * W + x - 1]);
        float phi[7];
        compute_phi(v, phi);
#pragma unroll
        for (int g = 0; g < 7; g++) E[((c * Yd + ly) * 7 + g) * Xd + x] = phi[g];
    }
}

// ---------------- layers 1/2: strip kernel, 64 threads, full-channel threads ----------------
template <int C, int H, int W, int O, int OT, int SR>
__global__ void __launch_bounds__(64, 8) kan_layer(
    const float* __restrict__ in, float* __restrict__ out, const float* __restrict__ Wg)
{
    constexpr int PW = W / 2, PH = H / 2;
    constexpr int OG = O / OT;
    constexpr int STRIPS = PH / SR;
    constexpr int Yd = 2 * SR + 2, Xd = W + 2;
    constexpr int THREADS = PW * SR * OG;
    static_assert(THREADS == 64, "block must be 64 threads");

    extern __shared__ float E[];

    const int b   = blockIdx.x / STRIPS;
    const int s   = blockIdx.x % STRIPS;
    const int tid = threadIdx.x;

    expand_strip<C, H, W, SR, THREADS>(in + (size_t)b * C * H * W, E, s, tid);
    __syncthreads();

    const int px = tid % PW;
    const int pr = (tid / PW) % SR;
    const int og = tid / (PW * SR);

    float acc[OT][4];
#pragma unroll
    for (int o = 0; o < OT; o++) acc[o][0] = acc[o][1] = acc[o][2] = acc[o][3] = 0.0f;

    conv_body<C, OT, Yd, Xd>(E, Wg, acc, 0, pr, px, og * OT * C, C);

    float* outb = out + (size_t)b * O * PH * PW;
    const int prow = s * SR + pr;
#pragma unroll
    for (int o = 0; o < OT; o++) {
        float m = fmaxf(fmaxf(acc[o][0], acc[o][1]), fmaxf(acc[o][2], acc[o][3]));
        outb[((og * OT + o) * PH + prow) * PW + px] = m;
    }
}

// ---------------- layer 3: channel-split (CS=2), 128 threads ----------------
// thread = (px, pr, og, cs); cs=1 writes partials to smem, cs=0 combines.
__global__ void __launch_bounds__(128, 4) kan_layer3(
    const float* __restrict__ in, float* __restrict__ out, const float* __restrict__ Wg)
{
    constexpr int C = 16, H = 8, W = 8, O = 32, OT = 4, SR = 2;
    constexpr int PW = W / 2, PH = H / 2;
    constexpr int OG = O / OT;                 // 8
    constexpr int STRIPS = PH / SR;            // 2
    constexpr int Yd = 2 * SR + 2, Xd = W + 2; // 6, 10
    constexpr int THREADS = 128;
    constexpr int HALF = 64;

    extern __shared__ float E[];               // 16*6*7*10 = 6720 floats

    const int b   = blockIdx.x / STRIPS;
    const int s   = blockIdx.x % STRIPS;
    const int tid = threadIdx.x;

    expand_strip<C, H, W, SR, THREADS>(in + (size_t)b * C * H * W, E, s, tid);
    __syncthreads();

    const int px = tid % PW;
    const int pr = (tid / PW) % SR;
    const int og = (tid / (PW * SR)) % OG;
    const int cs = tid / (PW * SR * OG);

    float acc[OT][4];
#pragma unroll
    for (int o = 0; o < OT; o++) acc[o][0] = acc[o][1] = acc[o][2] = acc[o][3] = 0.0f;

    conv_body<8, OT, Yd, Xd>(E, Wg, acc, cs * 8, pr, px, og * OT * C, C);

    __syncthreads();                            // all conv reads of E done
    float* P = E;                               // reuse arena: 64*17 = 1088 floats
    const int slot = tid % HALF;                // same (px,pr,og) pair across halves
    if (cs == 1) {
#pragma unroll
        for (int o = 0; o < OT; o++)
#pragma unroll
            for (int k = 0; k < 4; k++) P[slot * 17 + o * 4 + k] = acc[o][k];
    }
    __syncthreads();
    if (cs == 0) {
        float* outb = out + (size_t)b * O * PH * PW;
        const int prow = s * SR + pr;
#pragma unroll
        for (int o = 0; o < OT; o++) {
            float v0 = acc[o][0] + P[slot * 17 + o * 4 + 0];
            float v1 = acc[o][1] + P[slot * 17 + o * 4 + 1];
            float v2 = acc[o][2] + P[slot * 17 + o * 4 + 2];
            float v3 = acc[o][3] + P[slot * 17 + o * 4 + 3];
            float m = fmaxf(fmaxf(v0, v1), fmaxf(v2, v3));
            outb[((og * OT + o) * PH + prow) * PW + px] = m;
        }
    }
}

// ---------------- final linear 512 -> 100 (direct linw rows, float4) ----------------
__global__ void __launch_bounds__(128) linear_k(const float* __restrict__ linw,
                                                const float* __restrict__ bias,
                                                float* __restrict__ out) {
    __shared__ float hs[512];
    int b = blockIdx.x;
    for (int i = threadIdx.x; i < 512; i += 128) hs[i] = g_out3[b * 512 + i];
    __syncthreads();
    int j = threadIdx.x;
    if (j < 100) {
        float a = __ldg(&bias[j]);
        const float4* wr = reinterpret_cast<const float4*>(linw + (size_t)j * 512);
        const float4* h4 = reinterpret_cast<const float4*>(hs);
#pragma unroll 8
        for (int f = 0; f < 128; f++) {
            float4 w = __ldg(&wr[f]);
            float4 hv = h4[f];
            a += w.x * hv.x + w.y * hv.y + w.z * hv.z + w.w * hv.w;
        }
        out[(size_t)b * 100 + j] = a;
    }
}

extern "C" void kernel_launch(void* const* d_in, const int* in_sizes, int n_in,
                              void* d_out, int out_size) {
    const float* x     = (const float*)d_in[0];
    const float* c1bw  = (const float*)d_in[1];
    const float* c1sw  = (const float*)d_in[2];
    const float* c1sc  = (const float*)d_in[3];
    const float* c2bw  = (const float*)d_in[4];
    const float* c2sw  = (const float*)d_in[5];
    const float* c2sc  = (const float*)d_in[6];
    const float* c3bw  = (const float*)d_in[7];
    const float* c3sw  = (const float*)d_in[8];
    const float* c3sc  = (const float*)d_in[9];
    const float* linw  = (const float*)d_in[10];
    const float* linb  = (const float*)d_in[11];
    float* out = (float*)d_out;

    static float *p_W1, *p_W2, *p_W3, *p_o1, *p_o2, *p_o3;
    static bool init = false;
    if (!init) {
        cudaGetSymbolAddress((void**)&p_W1, g_W1);
        cudaGetSymbolAddress((void**)&p_W2, g_W2);
        cudaGetSymbolAddress((void**)&p_W3, g_W3);
        cudaGetSymbolAddress((void**)&p_o1, g_out1);
        cudaGetSymbolAddress((void**)&p_o2, g_out2);
        cudaGetSymbolAddress((void**)&p_o3, g_out3);
        init = true;
    }

    prep_all<<<(NPREP + 255) / 256, 256>>>(c1bw, c1sw, c1sc, c2bw, c2sw, c2sc,
                                           c3bw, c3sw, c3sc);

    // L1: C=3 O=8  OT=4 SR=2 -> 64 thr, 8 strips, grid 2048, smem 3*6*7*34*4  = 17136 B
    kan_layer<3, 32, 32, 8, 4, 2><<<BATCH * 8, 64, 3 * 6 * 7 * 34 * 4>>>(x, p_o1, p_W1);
    // L2: C=8 O=16 OT=4 SR=2 -> 64 thr, 4 strips, grid 1024, smem 8*6*7*18*4 = 24192 B
    kan_layer<8, 16, 16, 16, 4, 2><<<BATCH * 4, 64, 8 * 6 * 7 * 18 * 4>>>(p_o1, p_o2, p_W2);
    // L3: C=16 O=32 OT=4 SR=2 CS=2 -> 128 thr, 2 strips, grid 512, smem 16*6*7*10*4 = 26880 B
    kan_layer3<<<BATCH * 2, 128, 16 * 6 * 7 * 10 * 4>>>(p_o2, p_o3, p_W3);

    linear_k<<<BATCH, 128>>>(linw, linb, out);
}